// round 16
// baseline (speedup 1.0000x reference)
#include <cuda_runtime.h>
#include <cstdint>
#include <cstddef>

typedef unsigned int u32;

#define NN 4096
#define DD 128
#define NB 2
#define RHO 5
#define NJ 5
#define KC 64
#define PARTN ((size_t)NB * NN * DD)

// ---------------- device scratch ----------------
__device__ float g_part[2 * PARTN];            // split-K partials (K=2)
__device__ float g_xT[(size_t)NB * DD * NN];   // x^T, tf32-rounded fp32
__device__ float g_ZT[(size_t)NB * DD * NN];   // Z^T, tf32-rounded fp32
__device__ float g_F32[(size_t)NB * NN * 6 * DD]; // F, tf32-rounded fp32 [8192][768]
__device__ float g_WcT[DD * 6 * DD];           // Wc^T [128 d][768 k], tf32-rounded
__device__ float g_partial[NB * 32 * DD];
__device__ float g_acoef[NB * 8];
__device__ float g_bcoef[NB * 8];
__device__ float g_scale[NB * 8];
__device__ float g_cvec[DD];
__device__ int g_cnt[128];                     // gemm3 split-K arrival counters

// ---------------- helpers ----------------
__device__ __forceinline__ u32 smem_u32(const void* p) {
    u32 a;
    asm("{ .reg .u64 t; cvta.to.shared.u64 t, %1; cvt.u32.u64 %0, t; }" : "=r"(a) : "l"(p));
    return a;
}
__device__ __forceinline__ void ldsm4(u32 a, u32* r) {
    asm volatile("ldmatrix.sync.aligned.m8n8.x4.shared.b16 {%0,%1,%2,%3}, [%4];"
                 : "=r"(r[0]), "=r"(r[1]), "=r"(r[2]), "=r"(r[3]) : "r"(a));
}
__device__ __forceinline__ void mma1688t(float* c, const u32* a, const u32* b) {
    asm volatile(
        "mma.sync.aligned.m16n8k8.row.col.f32.tf32.tf32.f32 "
        "{%0,%1,%2,%3}, {%4,%5,%6,%7}, {%8,%9}, {%0,%1,%2,%3};"
        : "+f"(c[0]), "+f"(c[1]), "+f"(c[2]), "+f"(c[3])
        : "r"(a[0]), "r"(a[1]), "r"(a[2]), "r"(a[3]), "r"(b[0]), "r"(b[1]));
}
__device__ __forceinline__ float lds32(u32 a) {
    float v; asm volatile("ld.shared.f32 %0, [%1];" : "=f"(v) : "r"(a)); return v;
}
__device__ __forceinline__ u32 rna(float v) {
    u32 o; asm("cvt.rna.tf32.f32 %0, %1;" : "=r"(o) : "f"(v)); return o;
}
__device__ __forceinline__ float rnaf(float v) { return __uint_as_float(rna(v)); }

// ---------------- coefficient path ----------------
__global__ void partial_kernel(const float* __restrict__ eigvs) {
    int b = blockIdx.x >> 5, chunk = blockIdx.x & 31, d = threadIdx.x;
    const float* p = eigvs + ((size_t)b * NN + (size_t)chunk * 128) * DD + d;
    float s = 0.f;
#pragma unroll 8
    for (int r = 0; r < 128; r++) s += p[(size_t)r * DD];
    g_partial[(b * 32 + chunk) * DD + d] = s;
}

__global__ void coeff_kernel(const float* __restrict__ Wa, const float* __restrict__ ba,
                             const float* __restrict__ Wb, const float* __restrict__ bb,
                             const float* __restrict__ Ws, const float* __restrict__ bs) {
    __shared__ float red[15][128];
    int b = blockIdx.x, d = threadIdx.x;
    float s = 0.f;
    for (int c = 0; c < 32; c++) s += g_partial[(b * 32 + c) * DD + d];
    float m = s * (1.0f / NN);
#pragma unroll
    for (int j = 0; j < RHO; j++) {
        red[j][d] = m * Wa[d * RHO + j];
        red[5 + j][d] = m * Wb[d * RHO + j];
        red[10 + j][d] = m * Ws[d * NJ + j];
    }
    __syncthreads();
#pragma unroll
    for (int off = 64; off >= 1; off >>= 1) {
        for (int idx = d; idx < 15 * off; idx += 128) {
            int k = idx / off, e = idx - k * off;
            red[k][e] += red[k][e + off];
        }
        __syncthreads();
    }
    if (d < RHO) {
        g_acoef[b * 8 + d] = red[d][0] + ba[d];
        g_bcoef[b * 8 + d] = red[5 + d][0] + bb[d];
        float sv = red[10 + d][0] + bs[d];
        g_scale[b * 8 + d] = 5.0f / (1.0f + expf(-sv));
    }
}

// fold channel mats through Ww; output Wc^T [d][768] tf32-rounded
__global__ void weight_kernel(const float* __restrict__ WS_, const float* __restrict__ WM,
                              const float* __restrict__ Ww, const float* __restrict__ bS,
                              const float* __restrict__ bM, const float* __restrict__ bw) {
    int blk = blockIdx.x, d = threadIdx.x;
    if (blk < 6 * DD) {
        int s = blk >> 7, i = blk & 127;
        const float* wsrc = (s == 0) ? (WS_ + i * DD) : (WM + (size_t)(s - 1) * DD * DD + i * DD);
        float acc = 0.f;
        for (int e = 0; e < DD; e++) acc += wsrc[e] * Ww[e * DD + d];
        g_WcT[(size_t)d * (6 * DD) + blk] = rnaf(acc);
    } else {
        float acc = bw[d];
        for (int e = 0; e < DD; e++) {
            float cb = bS[e];
            for (int j = 0; j < NJ; j++) cb += bM[j * DD + e];
            acc += cb * Ww[e * DD + d];
        }
        g_cvec[d] = acc;
    }
}

// x -> x^T (tf32-rounded fp32)
__global__ void transpose_x_kernel(const float* __restrict__ x) {
    __shared__ float t[32][33];
    int tx = threadIdx.x, ty = threadIdx.y, b = blockIdx.z;
    int n0 = blockIdx.x * 32, d0 = blockIdx.y * 32;
#pragma unroll
    for (int j = 0; j < 4; j++)
        t[ty + 8 * j][tx] = x[((size_t)b * NN + n0 + ty + 8 * j) * DD + d0 + tx];
    __syncthreads();
#pragma unroll
    for (int j = 0; j < 4; j++)
        g_xT[(size_t)b * DD * NN + (size_t)(d0 + ty + 8 * j) * NN + n0 + tx] =
            rnaf(t[tx][ty + 8 * j]);
}

// fbuild: xt = sum of 2 split-K partials; F tf32-rounded; also resets gemm3 counters
__global__ void fbuild_kernel(const float* __restrict__ eigvs) {
    if (blockIdx.x == 0 && threadIdx.x < 128) g_cnt[threadIdx.x] = 0;
    int row0 = blockIdx.x * 16, d = threadIdx.x;
    for (int r = 0; r < 16; r++) {
        int row = row0 + r, b = row >> 12;
        const float* ac = g_acoef + b * 8;
        const float* bc = g_bcoef + b * 8;
        const float* sc = g_scale + b * 8;
        size_t idx = (size_t)row * DD + d;
        float e = eigvs[idx];
        float xv = g_part[idx] + g_part[PARTN + idx];
        float To = 1.f, Te = e, h = bc[0];
#pragma unroll
        for (int i = 1; i < RHO; i++) {
            To = 2.f * e * Te - To;
            Te = 2.f * e * To - Te;
            h += bc[i] * To;
        }
        size_t fb = (size_t)row * (6 * DD);
        g_F32[fb + d] = rnaf(h * xv);
#pragma unroll
        for (int j = 0; j < NJ; j++) {
            float sx = sc[j] * e;
            float To2 = 1.f, Te2 = sx, g = ac[0] * Te2;
#pragma unroll
            for (int i = 1; i < RHO; i++) {
                To2 = 2.f * sx * Te2 - To2;
                Te2 = 2.f * sx * To2 - Te2;
                g += ac[i] * Te2;
            }
            g_F32[fb + (1 + j) * DD + d] = rnaf(g * xv);
        }
    }
}

// ---------------- tf32 GEMM loaders ----------------
// TRANSA A (gemm1): smem [k][m], 64 k-rows x 256B, swizzle ch^((k&7)<<1)
__device__ __forceinline__ void loadA32T(u32 Ab, int k0, const float* A, int lda, int tid) {
#pragma unroll
    for (int i = 0; i < 8; i++) {
        int q = tid + i * 128;
        int row = q >> 4, ch = q & 15;
        const float* g = A + (size_t)(k0 + row) * lda + ch * 4;
        u32 dst = Ab + row * 256 + ((ch ^ ((row & 7) << 1)) << 4);
        asm volatile("cp.async.cg.shared.global [%0], [%1], 16;" :: "r"(dst), "l"(g));
    }
}
// ldsm-layout tile: smem [r][k], NR rows x 256B, swizzle ch^(row&15)
template <int NR>
__device__ __forceinline__ void loadTile32(u32 Tb, int k0, const float* S, int lds, int tid) {
#pragma unroll
    for (int i = 0; i < NR / 8; i++) {
        int q = tid + i * 128;
        int row = q >> 4, ch = q & 15;
        const float* g = S + (size_t)row * lds + k0 + ch * 4;
        u32 dst = Tb + row * 256 + ((ch ^ (row & 15)) << 4);
        asm volatile("cp.async.cg.shared.global [%0], [%1], 16;" :: "r"(dst), "l"(g));
    }
}

// B fragments via ldsm (pre-rounded source): NF/2 ldsm4 -> bf[NF][2]
template <int NF>
__device__ __forceinline__ void ldB32(u32 Bb, int s, int lane, int wn, u32 bf[][2]) {
    int rbase = ((lane >> 4) << 3) + (lane & 7);
    int ch = 2 * s + ((lane >> 3) & 1);
#pragma unroll
    for (int q = 0; q < NF / 2; q++) {
        int row = wn * (NF * 8) + q * 16 + rbase;
        u32 addr = Bb + row * 256 + ((ch ^ (row & 15)) << 4);
        u32 r[4];
        ldsm4(addr, r);
        bf[q * 2][0] = r[0]; bf[q * 2][1] = r[1];
        bf[q * 2 + 1][0] = r[2]; bf[q * 2 + 1][1] = r[3];
    }
}

// A fragments via ldsm; CVTA: apply rna (zero-bias) or feed raw fp32 (HW truncates)
template <bool CVTA>
__device__ __forceinline__ void ldA32(u32 Ab2, int s, int lane, int wm, int mt, u32* af) {
    int row = wm * 32 + mt * 16 + ((lane >> 3) & 1) * 8 + (lane & 7);
    int ch = 2 * s + (lane >> 4);
    u32 addr = Ab2 + row * 256 + ((ch ^ (row & 15)) << 4);
    u32 r[4];
    ldsm4(addr, r);
#pragma unroll
    for (int j = 0; j < 4; j++) af[j] = CVTA ? rna(__uint_as_float(r[j])) : r[j];
}

// ---------------- tf32 GEMM: BM=64 x BN, 128 thr, 2 stages ----------------
// OUTMODE 0: fp32 split-K partial; 1: Z^T rounded transposed; 2: fused split-K combine + bias
template <bool TRANSA, bool CVTA, int OUTMODE, int NSPLIT, int BN>
__global__ void __launch_bounds__(128, 2)
tf32_gemm(const float* __restrict__ A, const float* __restrict__ B,
          float* __restrict__ Cpart, float* __restrict__ Out, const float* __restrict__ bias,
          int K, int lda, int ldb, size_t aB, size_t bB) {
    constexpr int NF = BN / 16;
    constexpr u32 STAGE = 16384 + BN * 256;
    extern __shared__ char smem[];
    __shared__ int slast;
    u32 sb = smem_u32(smem);
    int tid = threadIdx.x, lane = tid & 31, wid = tid >> 5;
    int wm = wid & 1, wn = wid >> 1;
    int bx = blockIdx.x, nh = blockIdx.y;
    int bz = blockIdx.z / NSPLIT, ks = blockIdx.z % NSPLIT;
    const int Klocal = K / NSPLIT;
    const int kofs = ks * Klocal;

    A += bz * aB;
    if (TRANSA) A += (size_t)kofs * lda + (size_t)bx * 64;
    else        A += (size_t)bx * 64 * lda + kofs;
    B += bz * bB + (size_t)nh * BN * ldb + kofs;
    float* C = Cpart + (size_t)ks * PARTN + (size_t)bz * NN * DD;

    float acc[2][NF][4];
#pragma unroll
    for (int a = 0; a < 2; a++)
#pragma unroll
        for (int b = 0; b < NF; b++)
#pragma unroll
            for (int c = 0; c < 4; c++) acc[a][b][c] = 0.f;

    const int NCH = Klocal / KC;
#pragma unroll
    for (int s = 0; s < 2; s++) {
        u32 Ab = sb + s * STAGE;
        if (TRANSA) loadA32T(Ab, s * KC, A, lda, tid);
        else        loadTile32<64>(Ab, s * KC, A, lda, tid);
        loadTile32<BN>(Ab + 16384, s * KC, B, ldb, tid);
        asm volatile("cp.async.commit_group;" ::: "memory");
    }

    const int r = lane >> 2, c = lane & 3;

    u32 aoff[2][4];
    if (TRANSA) {
        int sw0 = c << 1, sw1 = (c + 4) << 1;
#pragma unroll
        for (int mt = 0; mt < 2; mt++) {
            int mb = wm * 32 + mt * 16;
            int mc0 = mb + r, mc1 = mb + r + 8;
            aoff[mt][0] = ((u32)((mc0 >> 2) ^ sw0) << 4) + ((mc0 & 3) << 2);
            aoff[mt][1] = ((u32)((mc1 >> 2) ^ sw0) << 4) + ((mc1 & 3) << 2);
            aoff[mt][2] = 1024u + ((u32)((mc0 >> 2) ^ sw1) << 4) + ((mc0 & 3) << 2);
            aoff[mt][3] = 1024u + ((u32)((mc1 >> 2) ^ sw1) << 4) + ((mc1 & 3) << 2);
        }
    }

    for (int cc = 0; cc < NCH; cc++) {
        int st = cc & 1;
        if (cc + 1 < NCH) asm volatile("cp.async.wait_group 1;" ::: "memory");
        else              asm volatile("cp.async.wait_group 0;" ::: "memory");
        __syncthreads();

        u32 Ab = sb + st * STAGE;
        u32 Bb = Ab + 16384;
#pragma unroll
        for (int s = 0; s < 8; s++) {
            u32 af[2][4], bf2[NF][2];
            if (TRANSA) {
                u32 base = Ab + (u32)(s * 8 + c) * 256;
#pragma unroll
                for (int mt = 0; mt < 2; mt++) {
                    af[mt][0] = rna(lds32(base + aoff[mt][0]));
                    af[mt][1] = rna(lds32(base + aoff[mt][1]));
                    af[mt][2] = rna(lds32(base + aoff[mt][2]));
                    af[mt][3] = rna(lds32(base + aoff[mt][3]));
                }
            } else {
#pragma unroll
                for (int mt = 0; mt < 2; mt++) ldA32<CVTA>(Ab, s, lane, wm, mt, af[mt]);
            }
            ldB32<NF>(Bb, s, lane, wn, bf2);
#pragma unroll
            for (int mt = 0; mt < 2; mt++)
#pragma unroll
                for (int nf = 0; nf < NF; nf++)
                    mma1688t(acc[mt][nf], af[mt], bf2[nf]);
        }
        __syncthreads();
        if (cc + 2 < NCH) {
            u32 Ab2 = sb + st * STAGE;
            if (TRANSA) loadA32T(Ab2, (cc + 2) * KC, A, lda, tid);
            else        loadTile32<64>(Ab2, (cc + 2) * KC, A, lda, tid);
            loadTile32<BN>(Ab2 + 16384, (cc + 2) * KC, B, ldb, tid);
            asm volatile("cp.async.commit_group;" ::: "memory");
        }
    }

    // epilogue
#pragma unroll
    for (int mt = 0; mt < 2; mt++)
#pragma unroll
        for (int nf = 0; nf < NF; nf++) {
            int mloc = bx * 64 + wm * 32 + mt * 16 + r;
            int col = nh * BN + wn * (NF * 8) + nf * 8 + c * 2;
#pragma unroll
            for (int rr = 0; rr < 2; rr++) {
                if (OUTMODE == 0 || OUTMODE == 2) {
                    size_t off = (size_t)(mloc + rr * 8) * 128 + col;
                    *(float2*)(C + off) = make_float2(acc[mt][nf][rr * 2], acc[mt][nf][rr * 2 + 1]);
                } else {
                    int m = mloc + rr * 8;
                    int b = m >> 12, n = m & 4095;
                    size_t base = (size_t)b * DD * NN + n;
                    g_ZT[base + (size_t)col * NN] = rnaf(acc[mt][nf][rr * 2]);
                    g_ZT[base + (size_t)(col + 1) * NN] = rnaf(acc[mt][nf][rr * 2 + 1]);
                }
            }
        }

    if (OUTMODE == 2) {
        // fused split-K combine + bias: last CTA per tile reduces (fixed order p0+p1)
        __threadfence();
        __syncthreads();
        if (tid == 0) slast = atomicAdd(&g_cnt[bx * NSPLIT + bz], 1);
        __syncthreads();
        if (slast == NSPLIT - 1) {
            __threadfence();
            const float* P0 = g_part + (size_t)bz * NN * DD;
            const float* P1 = g_part + PARTN + (size_t)bz * NN * DD;
            float* O = Out + (size_t)bz * NN * DD;
#pragma unroll
            for (int mt = 0; mt < 2; mt++)
#pragma unroll
                for (int nf = 0; nf < NF; nf++) {
                    int mloc = bx * 64 + wm * 32 + mt * 16 + r;
                    int col = nh * BN + wn * (NF * 8) + nf * 8 + c * 2;
#pragma unroll
                    for (int rr = 0; rr < 2; rr++) {
                        size_t off = (size_t)(mloc + rr * 8) * 128 + col;
                        float2 a = *(const float2*)(P0 + off);
                        float2 b = *(const float2*)(P1 + off);
                        *(float2*)(O + off) = make_float2(a.x + b.x + bias[col],
                                                          a.y + b.y + bias[col + 1]);
                    }
                }
        }
    }
}

// ---------------------------------------------------------------
extern "C" void kernel_launch(void* const* d_in, const int* in_sizes, int n_in,
                              void* d_out, int out_size) {
    const float* eigvs = (const float*)d_in[0];
    const float* x = (const float*)d_in[1];
    const float* U = (const float*)d_in[2];
    const float* Wa = (const float*)d_in[3];
    const float* ba = (const float*)d_in[4];
    const float* Wb = (const float*)d_in[5];
    const float* bb = (const float*)d_in[6];
    const float* Ws = (const float*)d_in[7];
    const float* bs = (const float*)d_in[8];
    const float* WS_ = (const float*)d_in[9];
    const float* bS = (const float*)d_in[10];
    const float* WM = (const float*)d_in[11];
    const float* bM = (const float*)d_in[12];
    const float* Ww = (const float*)d_in[13];
    const float* bw = (const float*)d_in[14];
    float* out = (float*)d_out;

    const int SM128 = 2 * (16384 + 128 * 256);   // 98304
    const int SM64 = 2 * (16384 + 64 * 256);     // 65536
    cudaFuncSetAttribute(tf32_gemm<true, true, 0, 2, 128>, cudaFuncAttributeMaxDynamicSharedMemorySize, SM128);
    cudaFuncSetAttribute(tf32_gemm<false, false, 2, 2, 128>, cudaFuncAttributeMaxDynamicSharedMemorySize, SM128);
    cudaFuncSetAttribute(tf32_gemm<false, false, 1, 1, 64>, cudaFuncAttributeMaxDynamicSharedMemorySize, SM64);

    float *pcv, *pp, *pxT, *pZT, *pF, *pW;
    cudaGetSymbolAddress((void**)&pcv, g_cvec);
    cudaGetSymbolAddress((void**)&pp, g_part);
    cudaGetSymbolAddress((void**)&pxT, g_xT);
    cudaGetSymbolAddress((void**)&pZT, g_ZT);
    cudaGetSymbolAddress((void**)&pF, g_F32);
    cudaGetSymbolAddress((void**)&pW, g_WcT);

    const size_t sU = (size_t)NN * NN;
    const size_t sT = (size_t)DD * NN;

    partial_kernel<<<64, 128>>>(eigvs);
    coeff_kernel<<<2, 128>>>(Wa, ba, Wb, bb, Ws, bs);
    weight_kernel<<<769, 128>>>(WS_, WM, Ww, bS, bM, bw);
    transpose_x_kernel<<<dim3(128, 4, 2), dim3(32, 8)>>>(x);

    // gemm1: xt[n][d] = sum_k U[k][n] x[k][d]; BN=128, split-K=2, partials -> fbuild
    tf32_gemm<true, true, 0, 2, 128><<<dim3(64, 1, 4), 128, SM128>>>(
        U, pxT, pp, nullptr, nullptr, NN, NN, NN, sU, sT);

    fbuild_kernel<<<512, 128>>>(eigvs);

    // gemm2: Z^T = (F @ Wc)^T; BN=64, K=768, pre-rounded both sides
    tf32_gemm<false, false, 1, 1, 64><<<dim3(128, 2, 1), 128, SM64>>>(
        pF, pW, nullptr, nullptr, nullptr, 6 * DD, 6 * DD, 6 * DD, 0, 0);

    // gemm3: out = U @ Z + cvec; BN=128, split-K=2, fused combine+bias, raw-U A (no cvt)
    tf32_gemm<false, false, 2, 2, 128><<<dim3(64, 1, 4), 128, SM128>>>(
        U, pZT, pp, out, pcv, NN, NN, NN, sU, sT);
}

// round 17
// speedup vs baseline: 1.1288x; 1.1288x over previous
#include <cuda_runtime.h>
#include <cstdint>
#include <cstddef>

typedef unsigned int u32;

#define NN 4096
#define DD 128
#define NB 2
#define RHO 5
#define NJ 5
#define KC 64
#define PARTN ((size_t)NB * NN * DD)

// ---------------- device scratch ----------------
__device__ float g_part[2 * PARTN];            // split-K partials (K=2)
__device__ float g_xT[(size_t)NB * DD * NN];   // x^T, tf32-rounded fp32
__device__ float g_ZT[(size_t)NB * DD * NN];   // Z^T, tf32-rounded fp32
__device__ float g_F32[(size_t)NB * NN * 6 * DD]; // F, tf32-rounded fp32 [8192][768]
__device__ float g_WcT[DD * 6 * DD];           // Wc^T [128 d][768 k], tf32-rounded
__device__ float g_partial[NB * 32 * DD];
__device__ float g_acoef[NB * 8];
__device__ float g_bcoef[NB * 8];
__device__ float g_scale[NB * 8];
__device__ float g_cvec[DD];

// ---------------- helpers ----------------
__device__ __forceinline__ u32 smem_u32(const void* p) {
    u32 a;
    asm("{ .reg .u64 t; cvta.to.shared.u64 t, %1; cvt.u32.u64 %0, t; }" : "=r"(a) : "l"(p));
    return a;
}
__device__ __forceinline__ void ldsm4(u32 a, u32* r) {
    asm volatile("ldmatrix.sync.aligned.m8n8.x4.shared.b16 {%0,%1,%2,%3}, [%4];"
                 : "=r"(r[0]), "=r"(r[1]), "=r"(r[2]), "=r"(r[3]) : "r"(a));
}
__device__ __forceinline__ void mma1688t(float* c, const u32* a, const u32* b) {
    asm volatile(
        "mma.sync.aligned.m16n8k8.row.col.f32.tf32.tf32.f32 "
        "{%0,%1,%2,%3}, {%4,%5,%6,%7}, {%8,%9}, {%0,%1,%2,%3};"
        : "+f"(c[0]), "+f"(c[1]), "+f"(c[2]), "+f"(c[3])
        : "r"(a[0]), "r"(a[1]), "r"(a[2]), "r"(a[3]), "r"(b[0]), "r"(b[1]));
}
__device__ __forceinline__ float lds32(u32 a) {
    float v; asm volatile("ld.shared.f32 %0, [%1];" : "=f"(v) : "r"(a)); return v;
}
__device__ __forceinline__ u32 rna(float v) {
    u32 o; asm("cvt.rna.tf32.f32 %0, %1;" : "=r"(o) : "f"(v)); return o;
}
__device__ __forceinline__ float rnaf(float v) { return __uint_as_float(rna(v)); }

// ---------------- coefficient path ----------------
__global__ void partial_kernel(const float* __restrict__ eigvs) {
    int b = blockIdx.x >> 5, chunk = blockIdx.x & 31, d = threadIdx.x;
    const float* p = eigvs + ((size_t)b * NN + (size_t)chunk * 128) * DD + d;
    float s = 0.f;
#pragma unroll 8
    for (int r = 0; r < 128; r++) s += p[(size_t)r * DD];
    g_partial[(b * 32 + chunk) * DD + d] = s;
}

__global__ void coeff_kernel(const float* __restrict__ Wa, const float* __restrict__ ba,
                             const float* __restrict__ Wb, const float* __restrict__ bb,
                             const float* __restrict__ Ws, const float* __restrict__ bs) {
    __shared__ float red[15][128];
    int b = blockIdx.x, d = threadIdx.x;
    float s = 0.f;
    for (int c = 0; c < 32; c++) s += g_partial[(b * 32 + c) * DD + d];
    float m = s * (1.0f / NN);
#pragma unroll
    for (int j = 0; j < RHO; j++) {
        red[j][d] = m * Wa[d * RHO + j];
        red[5 + j][d] = m * Wb[d * RHO + j];
        red[10 + j][d] = m * Ws[d * NJ + j];
    }
    __syncthreads();
#pragma unroll
    for (int off = 64; off >= 1; off >>= 1) {
        for (int idx = d; idx < 15 * off; idx += 128) {
            int k = idx / off, e = idx - k * off;
            red[k][e] += red[k][e + off];
        }
        __syncthreads();
    }
    if (d < RHO) {
        g_acoef[b * 8 + d] = red[d][0] + ba[d];
        g_bcoef[b * 8 + d] = red[5 + d][0] + bb[d];
        float sv = red[10 + d][0] + bs[d];
        g_scale[b * 8 + d] = 5.0f / (1.0f + expf(-sv));
    }
}

// fold channel mats through Ww; output Wc^T [d][768] tf32-rounded
__global__ void weight_kernel(const float* __restrict__ WS_, const float* __restrict__ WM,
                              const float* __restrict__ Ww, const float* __restrict__ bS,
                              const float* __restrict__ bM, const float* __restrict__ bw) {
    int blk = blockIdx.x, d = threadIdx.x;
    if (blk < 6 * DD) {
        int s = blk >> 7, i = blk & 127;
        const float* wsrc = (s == 0) ? (WS_ + i * DD) : (WM + (size_t)(s - 1) * DD * DD + i * DD);
        float acc = 0.f;
        for (int e = 0; e < DD; e++) acc += wsrc[e] * Ww[e * DD + d];
        g_WcT[(size_t)d * (6 * DD) + blk] = rnaf(acc);
    } else {
        float acc = bw[d];
        for (int e = 0; e < DD; e++) {
            float cb = bS[e];
            for (int j = 0; j < NJ; j++) cb += bM[j * DD + e];
            acc += cb * Ww[e * DD + d];
        }
        g_cvec[d] = acc;
    }
}

// x -> x^T (tf32-rounded fp32)
__global__ void transpose_x_kernel(const float* __restrict__ x) {
    __shared__ float t[32][33];
    int tx = threadIdx.x, ty = threadIdx.y, b = blockIdx.z;
    int n0 = blockIdx.x * 32, d0 = blockIdx.y * 32;
#pragma unroll
    for (int j = 0; j < 4; j++)
        t[ty + 8 * j][tx] = x[((size_t)b * NN + n0 + ty + 8 * j) * DD + d0 + tx];
    __syncthreads();
#pragma unroll
    for (int j = 0; j < 4; j++)
        g_xT[(size_t)b * DD * NN + (size_t)(d0 + ty + 8 * j) * NN + n0 + tx] =
            rnaf(t[tx][ty + 8 * j]);
}

// fbuild: xt = sum of 2 split-K partials; F output tf32-rounded fp32
__global__ void fbuild_kernel(const float* __restrict__ eigvs) {
    int row0 = blockIdx.x * 16, d = threadIdx.x;
    for (int r = 0; r < 16; r++) {
        int row = row0 + r, b = row >> 12;
        const float* ac = g_acoef + b * 8;
        const float* bc = g_bcoef + b * 8;
        const float* sc = g_scale + b * 8;
        size_t idx = (size_t)row * DD + d;
        float e = eigvs[idx];
        float xv = g_part[idx] + g_part[PARTN + idx];
        float To = 1.f, Te = e, h = bc[0];
#pragma unroll
        for (int i = 1; i < RHO; i++) {
            To = 2.f * e * Te - To;
            Te = 2.f * e * To - Te;
            h += bc[i] * To;
        }
        size_t fb = (size_t)row * (6 * DD);
        g_F32[fb + d] = rnaf(h * xv);
#pragma unroll
        for (int j = 0; j < NJ; j++) {
            float sx = sc[j] * e;
            float To2 = 1.f, Te2 = sx, g = ac[0] * Te2;
#pragma unroll
            for (int i = 1; i < RHO; i++) {
                To2 = 2.f * sx * Te2 - To2;
                Te2 = 2.f * sx * To2 - Te2;
                g += ac[i] * Te2;
            }
            g_F32[fb + (1 + j) * DD + d] = rnaf(g * xv);
        }
    }
}

__global__ void combine2_bias_kernel(const float* __restrict__ bias, float* __restrict__ dst) {
    size_t i = (size_t)blockIdx.x * blockDim.x + threadIdx.x;
    int col = ((int)(i & 31)) * 4;
    const float4* p = (const float4*)g_part;
    const size_t q = PARTN / 4;
    float4 a = p[i], b = p[q + i];
    ((float4*)dst)[i] = make_float4(a.x + b.x + bias[col], a.y + b.y + bias[col + 1],
                                    a.z + b.z + bias[col + 2], a.w + b.w + bias[col + 3]);
}

// ---------------- tf32 GEMM loaders ----------------
// TRANSA A (gemm1): smem [k][m], 64 k-rows x 256B, swizzle ch^((k&7)<<1)
__device__ __forceinline__ void loadA32T(u32 Ab, int k0, const float* A, int lda, int tid) {
#pragma unroll
    for (int i = 0; i < 8; i++) {
        int q = tid + i * 128;
        int row = q >> 4, ch = q & 15;
        const float* g = A + (size_t)(k0 + row) * lda + ch * 4;
        u32 dst = Ab + row * 256 + ((ch ^ ((row & 7) << 1)) << 4);
        asm volatile("cp.async.cg.shared.global [%0], [%1], 16;" :: "r"(dst), "l"(g));
    }
}
// ldsm-layout tile: smem [r][k], NR rows x 256B, swizzle ch^(row&15)
template <int NR>
__device__ __forceinline__ void loadTile32(u32 Tb, int k0, const float* S, int lds, int tid) {
#pragma unroll
    for (int i = 0; i < NR / 8; i++) {
        int q = tid + i * 128;
        int row = q >> 4, ch = q & 15;
        const float* g = S + (size_t)row * lds + k0 + ch * 4;
        u32 dst = Tb + row * 256 + ((ch ^ (row & 15)) << 4);
        asm volatile("cp.async.cg.shared.global [%0], [%1], 16;" :: "r"(dst), "l"(g));
    }
}

// B fragments via ldsm (pre-rounded source): NF/2 ldsm4 -> bf[NF][2]
template <int NF>
__device__ __forceinline__ void ldB32(u32 Bb, int s, int lane, int wn, u32 bf[][2]) {
    int rbase = ((lane >> 4) << 3) + (lane & 7);
    int ch = 2 * s + ((lane >> 3) & 1);
#pragma unroll
    for (int q = 0; q < NF / 2; q++) {
        int row = wn * (NF * 8) + q * 16 + rbase;
        u32 addr = Bb + row * 256 + ((ch ^ (row & 15)) << 4);
        u32 r[4];
        ldsm4(addr, r);
        bf[q * 2][0] = r[0]; bf[q * 2][1] = r[1];
        bf[q * 2 + 1][0] = r[2]; bf[q * 2 + 1][1] = r[3];
    }
}

// A fragments via ldsm; CVTA: apply rna (zero-bias) or feed raw fp32 (HW truncates)
template <bool CVTA>
__device__ __forceinline__ void ldA32(u32 Ab2, int s, int lane, int wm, int mt, u32* af) {
    int row = wm * 32 + mt * 16 + ((lane >> 3) & 1) * 8 + (lane & 7);
    int ch = 2 * s + (lane >> 4);
    u32 addr = Ab2 + row * 256 + ((ch ^ (row & 15)) << 4);
    u32 r[4];
    ldsm4(addr, r);
#pragma unroll
    for (int j = 0; j < 4; j++) af[j] = CVTA ? rna(__uint_as_float(r[j])) : r[j];
}

// ---------------- tf32 GEMM: BM=64 x BN, 128 thr, 2 stages ----------------
// warp layout: wm = wid&1 (32-row half), wn = wid>>1 (BN/2-col half); NF = BN/16 frags/warp.
// OUTMODE 0: fp32 split-K partial [m][128]; OUTMODE 1: Z^T rounded transposed
template <bool TRANSA, bool CVTA, int OUTMODE, int NSPLIT, int BN>
__global__ void __launch_bounds__(128, 2)
tf32_gemm(const float* __restrict__ A, const float* __restrict__ B,
          float* __restrict__ Cpart, int K, int lda, int ldb,
          size_t aB, size_t bB) {
    constexpr int NF = BN / 16;
    constexpr u32 STAGE = 16384 + BN * 256;
    extern __shared__ char smem[];
    u32 sb = smem_u32(smem);
    int tid = threadIdx.x, lane = tid & 31, wid = tid >> 5;
    int wm = wid & 1, wn = wid >> 1;
    int bx = blockIdx.x, nh = blockIdx.y;
    int bz = blockIdx.z / NSPLIT, ks = blockIdx.z % NSPLIT;
    const int Klocal = K / NSPLIT;
    const int kofs = ks * Klocal;

    A += bz * aB;
    if (TRANSA) A += (size_t)kofs * lda + (size_t)bx * 64;
    else        A += (size_t)bx * 64 * lda + kofs;
    B += bz * bB + (size_t)nh * BN * ldb + kofs;
    float* C = Cpart + (size_t)ks * PARTN + (size_t)bz * NN * DD;

    float acc[2][NF][4];
#pragma unroll
    for (int a = 0; a < 2; a++)
#pragma unroll
        for (int b = 0; b < NF; b++)
#pragma unroll
            for (int c = 0; c < 4; c++) acc[a][b][c] = 0.f;

    const int NCH = Klocal / KC;
#pragma unroll
    for (int s = 0; s < 2; s++) {
        u32 Ab = sb + s * STAGE;
        if (TRANSA) loadA32T(Ab, s * KC, A, lda, tid);
        else        loadTile32<64>(Ab, s * KC, A, lda, tid);
        loadTile32<BN>(Ab + 16384, s * KC, B, ldb, tid);
        asm volatile("cp.async.commit_group;" ::: "memory");
    }

    const int r = lane >> 2, c = lane & 3;

    // hoisted scalar-A swizzle offsets (TRANSA path)
    u32 aoff[2][4];
    if (TRANSA) {
        int sw0 = c << 1, sw1 = (c + 4) << 1;
#pragma unroll
        for (int mt = 0; mt < 2; mt++) {
            int mb = wm * 32 + mt * 16;
            int mc0 = mb + r, mc1 = mb + r + 8;
            aoff[mt][0] = ((u32)((mc0 >> 2) ^ sw0) << 4) + ((mc0 & 3) << 2);
            aoff[mt][1] = ((u32)((mc1 >> 2) ^ sw0) << 4) + ((mc1 & 3) << 2);
            aoff[mt][2] = 1024u + ((u32)((mc0 >> 2) ^ sw1) << 4) + ((mc0 & 3) << 2);
            aoff[mt][3] = 1024u + ((u32)((mc1 >> 2) ^ sw1) << 4) + ((mc1 & 3) << 2);
        }
    }

    for (int cc = 0; cc < NCH; cc++) {
        int st = cc & 1;
        if (cc + 1 < NCH) asm volatile("cp.async.wait_group 1;" ::: "memory");
        else              asm volatile("cp.async.wait_group 0;" ::: "memory");
        __syncthreads();

        u32 Ab = sb + st * STAGE;
        u32 Bb = Ab + 16384;
#pragma unroll
        for (int s = 0; s < 8; s++) {
            u32 af[2][4], bf2[NF][2];
            if (TRANSA) {
                u32 base = Ab + (u32)(s * 8 + c) * 256;
#pragma unroll
                for (int mt = 0; mt < 2; mt++) {
                    af[mt][0] = rna(lds32(base + aoff[mt][0]));
                    af[mt][1] = rna(lds32(base + aoff[mt][1]));
                    af[mt][2] = rna(lds32(base + aoff[mt][2]));
                    af[mt][3] = rna(lds32(base + aoff[mt][3]));
                }
            } else {
#pragma unroll
                for (int mt = 0; mt < 2; mt++) ldA32<CVTA>(Ab, s, lane, wm, mt, af[mt]);
            }
            ldB32<NF>(Bb, s, lane, wn, bf2);
#pragma unroll
            for (int mt = 0; mt < 2; mt++)
#pragma unroll
                for (int nf = 0; nf < NF; nf++)
                    mma1688t(acc[mt][nf], af[mt], bf2[nf]);
        }
        __syncthreads();
        if (cc + 2 < NCH) {
            u32 Ab2 = sb + st * STAGE;
            if (TRANSA) loadA32T(Ab2, (cc + 2) * KC, A, lda, tid);
            else        loadTile32<64>(Ab2, (cc + 2) * KC, A, lda, tid);
            loadTile32<BN>(Ab2 + 16384, (cc + 2) * KC, B, ldb, tid);
            asm volatile("cp.async.commit_group;" ::: "memory");
        }
    }

    // epilogue
#pragma unroll
    for (int mt = 0; mt < 2; mt++)
#pragma unroll
        for (int nf = 0; nf < NF; nf++) {
            int mloc = bx * 64 + wm * 32 + mt * 16 + r;
            int col = nh * BN + wn * (NF * 8) + nf * 8 + c * 2;
#pragma unroll
            for (int rr = 0; rr < 2; rr++) {
                if (OUTMODE == 0) {
                    size_t off = (size_t)(mloc + rr * 8) * 128 + col;
                    *(float2*)(C + off) = make_float2(acc[mt][nf][rr * 2], acc[mt][nf][rr * 2 + 1]);
                } else {
                    int m = mloc + rr * 8;
                    int b = m >> 12, n = m & 4095;
                    size_t base = (size_t)b * DD * NN + n;
                    g_ZT[base + (size_t)col * NN] = rnaf(acc[mt][nf][rr * 2]);
                    g_ZT[base + (size_t)(col + 1) * NN] = rnaf(acc[mt][nf][rr * 2 + 1]);
                }
            }
        }
}

// ---------------------------------------------------------------
extern "C" void kernel_launch(void* const* d_in, const int* in_sizes, int n_in,
                              void* d_out, int out_size) {
    const float* eigvs = (const float*)d_in[0];
    const float* x = (const float*)d_in[1];
    const float* U = (const float*)d_in[2];
    const float* Wa = (const float*)d_in[3];
    const float* ba = (const float*)d_in[4];
    const float* Wb = (const float*)d_in[5];
    const float* bb = (const float*)d_in[6];
    const float* Ws = (const float*)d_in[7];
    const float* bs = (const float*)d_in[8];
    const float* WS_ = (const float*)d_in[9];
    const float* bS = (const float*)d_in[10];
    const float* WM = (const float*)d_in[11];
    const float* bM = (const float*)d_in[12];
    const float* Ww = (const float*)d_in[13];
    const float* bw = (const float*)d_in[14];
    float* out = (float*)d_out;

    const int SM128 = 2 * (16384 + 128 * 256);   // 98304
    const int SM64 = 2 * (16384 + 64 * 256);     // 65536
    cudaFuncSetAttribute(tf32_gemm<true, true, 0, 2, 128>, cudaFuncAttributeMaxDynamicSharedMemorySize, SM128);
    cudaFuncSetAttribute(tf32_gemm<false, false, 0, 2, 128>, cudaFuncAttributeMaxDynamicSharedMemorySize, SM128);
    cudaFuncSetAttribute(tf32_gemm<false, false, 1, 1, 64>, cudaFuncAttributeMaxDynamicSharedMemorySize, SM64);

    float *pcv, *pp, *pxT, *pZT, *pF, *pW;
    cudaGetSymbolAddress((void**)&pcv, g_cvec);
    cudaGetSymbolAddress((void**)&pp, g_part);
    cudaGetSymbolAddress((void**)&pxT, g_xT);
    cudaGetSymbolAddress((void**)&pZT, g_ZT);
    cudaGetSymbolAddress((void**)&pF, g_F32);
    cudaGetSymbolAddress((void**)&pW, g_WcT);

    const size_t sU = (size_t)NN * NN;
    const size_t sT = (size_t)DD * NN;

    partial_kernel<<<64, 128>>>(eigvs);
    coeff_kernel<<<2, 128>>>(Wa, ba, Wb, bb, Ws, bs);
    weight_kernel<<<769, 128>>>(WS_, WM, Ww, bS, bM, bw);
    transpose_x_kernel<<<dim3(128, 4, 2), dim3(32, 8)>>>(x);

    // gemm1: xt[n][d] = sum_k U[k][n] x[k][d]; BN=128, split-K=2 (rna on A: error feeds F)
    tf32_gemm<true, true, 0, 2, 128><<<dim3(64, 1, 4), 128, SM128>>>(
        U, pxT, pp, NN, NN, NN, sU, sT);

    fbuild_kernel<<<512, 128>>>(eigvs);

    // gemm2: Z^T = (F @ Wc)^T; BN=64, K=768, pre-rounded both sides
    tf32_gemm<false, false, 1, 1, 64><<<dim3(128, 2, 1), 128, SM64>>>(
        pF, pW, nullptr, 6 * DD, 6 * DD, 6 * DD, 0, 0);

    // gemm3: out = U @ Z; BN=128, split-K=2, raw-U A fragments (no cvt, HW truncation)
    tf32_gemm<false, false, 0, 2, 128><<<dim3(64, 1, 4), 128, SM128>>>(
        U, pZT, pp, NN, NN, NN, sU, sT);

    combine2_bias_kernel<<<1024, 256>>>(pcv, out);
}